// round 16
// baseline (speedup 1.0000x reference)
#include <cuda_runtime.h>

#define TT 64
#define BB 256
#define DD 512

// pre-activations, K2-block-contiguous layout:
// g_pre2[bblk(32)][t(64)][bloc(8)][gate(4)][q(6)]
__device__ __align__(16) float g_pre2[TT * BB * 24];

// ---------------------------------------------------------------------------
// K1: pre[t,b,g,q] = inputs[t,b,:] @ Wg[:512,q] + bg[q] + theta_g[q]
// R14 kernel + split-W layout: per (dd,gate), (w0,w1,w4,w5) in WA (16B-aligned
// -> one LDS.128) and (w2,w3) in WB (LDS.64). Inner loop: 3 LDS per d vs 4.
// Profile-driven: R15 ncu showed K1 L1-pipe-bound (L1 41%, fma 18%, issue 29%).
// ---------------------------------------------------------------------------
__global__ void __launch_bounds__(256, 1) k1_gemm(
    const float* __restrict__ X,
    const float* __restrict__ Wf, const float* __restrict__ bf,
    const float* __restrict__ Wi, const float* __restrict__ bi,
    const float* __restrict__ Wu, const float* __restrict__ bu,
    const float* __restrict__ Wo, const float* __restrict__ bo,
    const float* __restrict__ thf, const float* __restrict__ thi,
    const float* __restrict__ thu, const float* __restrict__ tho)
{
    __shared__ __align__(16) float WA[256 * 16];  // (w0,w1,w4,w5) per dd,gate 16KB
    __shared__ __align__(16) float WB[256 * 8];   // (w2,w3)       per dd,gate  8KB
    __shared__ float Xsh[32 * 130];               // x tile transposed [d][row]

    const int tid  = threadIdx.x;
    const int warp = tid >> 5;
    const int lane = tid & 31;
    const int gate = warp & 3;
    const int rloc = ((warp >> 2) << 6) + (lane << 1);   // block-local row (even)
    const int rowbase = blockIdx.x << 7;

    const float* bg = (gate == 0) ? bf  : (gate == 1) ? bi  : (gate == 2) ? bu  : bo;
    const float* tg = (gate == 0) ? thf : (gate == 1) ? thi : (gate == 2) ? thu : tho;

    unsigned long long a0[3], a1[3];
#pragma unroll
    for (int p = 0; p < 3; p++) {
        float blo = __ldg(bg + 2 * p + 0) + __ldg(tg + 2 * p + 0);
        float bhi = __ldg(bg + 2 * p + 1) + __ldg(tg + 2 * p + 1);
        unsigned long long bp;
        asm("mov.b64 %0, {%1, %2};" : "=l"(bp) : "f"(blo), "f"(bhi));
        a0[p] = bp;
        a1[p] = bp;
    }

    const int cc = tid & 7;   // d-group for staging
    const int rr = tid >> 3;  // row for staging

    // prologue: prefetch X tile 0 into registers
    float4 xr0, xr1, xr2, xr3;
    {
        const float4* xb = reinterpret_cast<const float4*>(X) + cc;
        xr0 = __ldg(xb + (size_t)(rowbase + rr +  0) * (DD / 4));
        xr1 = __ldg(xb + (size_t)(rowbase + rr + 32) * (DD / 4));
        xr2 = __ldg(xb + (size_t)(rowbase + rr + 64) * (DD / 4));
        xr3 = __ldg(xb + (size_t)(rowbase + rr + 96) * (DD / 4));
    }

    for (int kh = 0; kh < 2; kh++) {
        __syncthreads();  // prior compute done before W overwrite
        // stage W half kh into split layout
#pragma unroll
        for (int k = 0; k < 24; k++) {
            int idx = tid + (k << 8);          // 0..6143 == dd*24 + col
            int dd  = idx / 24;
            int col = idx - dd * 24;
            int g2  = col / 6;
            int q2  = col - g2 * 6;
            const float* Ws = (g2 == 0) ? Wf : (g2 == 1) ? Wi : (g2 == 2) ? Wu : Wo;
            float w = Ws[((kh << 8) + dd) * 6 + q2];
            if (q2 < 2)       WA[(dd << 4) + (g2 << 2) + q2]       = w;
            else if (q2 >= 4) WA[(dd << 4) + (g2 << 2) + q2 - 2]   = w;
            else              WB[(dd << 3) + (g2 << 1) + q2 - 2]   = w;
        }
        for (int tile = 0; tile < 8; tile++) {
            __syncthreads();  // W ready (tile 0) / Xsh free (prior compute done)
            {
                const int c4 = cc << 2;
                Xsh[(c4 + 0) * 130 + rr +  0] = xr0.x;
                Xsh[(c4 + 1) * 130 + rr +  0] = xr0.y;
                Xsh[(c4 + 2) * 130 + rr +  0] = xr0.z;
                Xsh[(c4 + 3) * 130 + rr +  0] = xr0.w;
                Xsh[(c4 + 0) * 130 + rr + 32] = xr1.x;
                Xsh[(c4 + 1) * 130 + rr + 32] = xr1.y;
                Xsh[(c4 + 2) * 130 + rr + 32] = xr1.z;
                Xsh[(c4 + 3) * 130 + rr + 32] = xr1.w;
                Xsh[(c4 + 0) * 130 + rr + 64] = xr2.x;
                Xsh[(c4 + 1) * 130 + rr + 64] = xr2.y;
                Xsh[(c4 + 2) * 130 + rr + 64] = xr2.z;
                Xsh[(c4 + 3) * 130 + rr + 64] = xr2.w;
                Xsh[(c4 + 0) * 130 + rr + 96] = xr3.x;
                Xsh[(c4 + 1) * 130 + rr + 96] = xr3.y;
                Xsh[(c4 + 2) * 130 + rr + 96] = xr3.z;
                Xsh[(c4 + 3) * 130 + rr + 96] = xr3.w;
            }
            __syncthreads();  // Xsh ready

            const int gtn = (kh << 3) + tile + 1;
            if (gtn < 16) {
                const float4* xb = reinterpret_cast<const float4*>(X) + (gtn << 3) + cc;
                xr0 = __ldg(xb + (size_t)(rowbase + rr +  0) * (DD / 4));
                xr1 = __ldg(xb + (size_t)(rowbase + rr + 32) * (DD / 4));
                xr2 = __ldg(xb + (size_t)(rowbase + rr + 64) * (DD / 4));
                xr3 = __ldg(xb + (size_t)(rowbase + rr + 96) * (DD / 4));
            }

#pragma unroll
            for (int d = 0; d < 32; d++) {
                const int dd = (tile << 5) + d;
                // one LDS.128: (w01, w45); one LDS.64: w23  (broadcast)
                const ulonglong2 wAv = *reinterpret_cast<const ulonglong2*>(
                    &WA[(dd << 4) + (gate << 2)]);
                const unsigned long long w01 = wAv.x;
                const unsigned long long w45 = wAv.y;
                const unsigned long long w23 = *reinterpret_cast<const unsigned long long*>(
                    &WB[(dd << 3) + (gate << 1)]);
                const float2 x2 = *reinterpret_cast<const float2*>(&Xsh[d * 130 + rloc]);
                unsigned long long xa, xb2;
                asm("mov.b64 %0, {%1, %1};" : "=l"(xa)  : "f"(x2.x));
                asm("mov.b64 %0, {%1, %1};" : "=l"(xb2) : "f"(x2.y));
                asm("fma.rn.f32x2 %0, %1, %2, %0;" : "+l"(a0[0]) : "l"(w01), "l"(xa));
                asm("fma.rn.f32x2 %0, %1, %2, %0;" : "+l"(a0[1]) : "l"(w23), "l"(xa));
                asm("fma.rn.f32x2 %0, %1, %2, %0;" : "+l"(a0[2]) : "l"(w45), "l"(xa));
                asm("fma.rn.f32x2 %0, %1, %2, %0;" : "+l"(a1[0]) : "l"(w01), "l"(xb2));
                asm("fma.rn.f32x2 %0, %1, %2, %0;" : "+l"(a1[1]) : "l"(w23), "l"(xb2));
                asm("fma.rn.f32x2 %0, %1, %2, %0;" : "+l"(a1[2]) : "l"(w45), "l"(xb2));
            }
        }
    }

    const int t = rowbase >> 8;
    const int b = (rowbase & 255) + rloc;       // even; b+1 shares b>>3
    float* dst = g_pre2 + ((size_t)((b >> 3) * 64 + t) * 192) + (b & 7) * 24 + gate * 6;
    unsigned long long* d64 = reinterpret_cast<unsigned long long*>(dst);
    d64[0] = a0[0]; d64[1] = a0[1]; d64[2] = a0[2];
    unsigned long long* e64 = reinterpret_cast<unsigned long long*>(dst + 24);
    e64[0] = a1[0]; e64[1] = a1[1]; e64[2] = a1[2];
}

// tanh via CF rational, one rcp; err <= ~2e-5 for |x| <= 2.2 (|c| <= 2.08).
__device__ __forceinline__ float tanh_rat(float x) {
    float s = x * x;
    float num = fmaf(s, fmaf(s, 21.0f, 1260.0f), 10395.0f);
    float den = fmaf(s, fmaf(s, s + 210.0f, 4725.0f), 10395.0f);
    float r;
    asm("rcp.approx.f32 %0, %1;" : "=f"(r) : "f"(den));
    return x * num * r;
}

// ---------------------------------------------------------------------------
// K2: EXACT R11 kernel (best measured: 17.2us).
// ---------------------------------------------------------------------------
__global__ void __launch_bounds__(128, 1) k2_scan(
    const float* __restrict__ Wf, const float* __restrict__ Wi,
    const float* __restrict__ Wu, const float* __restrict__ Wo,
    float* __restrict__ out)
{
    __shared__ float ps[TT * 192];    // 48KB : [t][bloc(8)][gate][q]

    const int tid = threadIdx.x;

    {
        const float4* src = reinterpret_cast<const float4*>(g_pre2 + (size_t)blockIdx.x * (TT * 192));
        float4* dst = reinterpret_cast<float4*>(ps);
#pragma unroll
        for (int i = 0; i < (TT * 192) / 4 / 128; i++)
            dst[tid + i * 128] = src[tid + i * 128];
    }
    __syncthreads();
    if (tid >= 64) return;

    const int lane = tid & 31;
    const int wrp  = tid >> 5;            // 0 or 1
    const int qh   = lane & 1;            // wire half
    const int g    = (lane >> 1) & 3;     // gate
    const int bl   = lane >> 3;           // batch within warp (0..3)
    const int bloc = (wrp << 2) + bl;     // batch within block (0..7)
    const int b    = (blockIdx.x << 3) + bloc;
    const int q0   = 3 * qh;
    const float* Wg = (g == 0) ? Wf : (g == 1) ? Wi : (g == 2) ? Wu : Wo;

    float Whk[6][3];
#pragma unroll
    for (int k = 0; k < 6; k++)
#pragma unroll
        for (int j = 0; j < 3; j++)
            Whk[k][j] = __ldg(Wg + (DD + k) * 6 + q0 + j);

    float h6[6];
#pragma unroll
    for (int k = 0; k < 6; k++) h6[k] = 0.0f;
    float c[3] = { 0.0f, 0.0f, 0.0f };

    const float* pb = ps + bloc * 24 + g * 6 + q0;
    const unsigned mask = 0xffffffffu;
    const int lb  = (lane & 24) | qh;     // gate-0 lane of this (batch, qh)
    const bool isU = (g == 2);
    const float cmul = isU ? -2.0f : -1.0f;
    const bool store = (g == 0);

#pragma unroll 2
    for (int t = 0; t < TT; t++) {
        const float p0 = pb[t * 192 + 0];
        const float p1 = pb[t * 192 + 1];
        const float p2 = pb[t * 192 + 2];

        float a[3];
        {
            float pj[3] = { p0, p1, p2 };
#pragma unroll
            for (int j = 0; j < 3; j++) {
                float u0 = fmaf(h6[0], Whk[0][j], fmaf(h6[1], Whk[1][j], fmaf(h6[2], Whk[2][j], pj[j])));
                float u1 = fmaf(h6[3], Whk[3][j], fmaf(h6[4], Whk[4][j], h6[5] * Whk[5][j]));
                a[j] = u0 + u1;
            }
        }

        float z0 = __cosf(a[0]);
        float z1 = __cosf(a[1]);
        float z2 = __cosf(a[2]);

        float zp0 = __shfl_xor_sync(mask, z0, 1);
        float zp1 = __shfl_xor_sync(mask, z1, 1);
        float zp2 = __shfl_xor_sync(mask, z2, 1);
        float zA0 = qh ? zp0 : z0;   // q0
        float zA1 = qh ? zp1 : z1;   // q1
        float zA2 = qh ? zp2 : z2;   // q2
        float zB0 = qh ? z0 : zp0;   // q3
        float zB1 = qh ? z1 : zp1;   // q4
        float zB2 = qh ? z2 : zp2;   // q5

        float z01 = zA0 * zA1;
        float z23 = zA2 * zB0;
        float z45 = zB1 * zB2;
        float w3  = z01 * z23;
        float wv0 = qh ? w3        : zA1 * (z23 * z45);   // w3 : w0
        float wv1 = qh ? w3 * zB1  : z01;                 // w4 : w1
        float wv2 = qh ? w3 * z45  : z01 * zA2;           // w5 : w2

        float v0, v1, v2;
        {
            float e0 = __expf(cmul * wv0);
            float e1 = __expf(cmul * wv1);
            float e2 = __expf(cmul * wv2);
            float s0 = __fdividef(1.0f, 1.0f + e0);
            float s1 = __fdividef(1.0f, 1.0f + e1);
            float s2 = __fdividef(1.0f, 1.0f + e2);
            v0 = isU ? fmaf(2.0f, s0, -1.0f) : s0;
            v1 = isU ? fmaf(2.0f, s1, -1.0f) : s1;
            v2 = isU ? fmaf(2.0f, s2, -1.0f) : s2;
        }

        float hq[3];
#pragma unroll
        for (int j = 0; j < 3; j++) {
            float vj = (j == 0) ? v0 : (j == 1) ? v1 : v2;
            float fq = __shfl_sync(mask, vj, lb + 0);
            float iq = __shfl_sync(mask, vj, lb + 2);
            float uq = __shfl_sync(mask, vj, lb + 4);
            float oq = __shfl_sync(mask, vj, lb + 6);
            float cn = fmaf(fq, c[j], iq * uq);
            c[j] = cn;
            hq[j] = oq * tanh_rat(cn);     // |cn| <= 2.08 guaranteed
        }

        if (store) {
            float* o0 = out + ((size_t)t * BB + b) * 6 + q0;
            o0[0] = hq[0]; o0[1] = hq[1]; o0[2] = hq[2];
        }

        float hp0 = __shfl_xor_sync(mask, hq[0], 1);
        float hp1 = __shfl_xor_sync(mask, hq[1], 1);
        float hp2 = __shfl_xor_sync(mask, hq[2], 1);
        h6[0] = qh ? hp0 : hq[0];
        h6[1] = qh ? hp1 : hq[1];
        h6[2] = qh ? hp2 : hq[2];
        h6[3] = qh ? hq[0] : hp0;
        h6[4] = qh ? hq[1] : hp1;
        h6[5] = qh ? hq[2] : hp2;
    }

    if (store) {
        float* hx = out + (size_t)TT * BB * 6 + (size_t)b * 6 + q0;
        float* cx = hx + BB * 6;
        hx[0] = qh ? h6[3] : h6[0];
        hx[1] = qh ? h6[4] : h6[1];
        hx[2] = qh ? h6[5] : h6[2];
        cx[0] = c[0]; cx[1] = c[1]; cx[2] = c[2];
    }
}

extern "C" void kernel_launch(void* const* d_in, const int* in_sizes, int n_in,
                              void* d_out, int out_size)
{
    const float* X   = (const float*)d_in[0];
    const float* Wf  = (const float*)d_in[1];
    const float* bf  = (const float*)d_in[2];
    const float* Wi  = (const float*)d_in[3];
    const float* bi  = (const float*)d_in[4];
    const float* Wu  = (const float*)d_in[5];
    const float* bu  = (const float*)d_in[6];
    const float* Wo  = (const float*)d_in[7];
    const float* bo  = (const float*)d_in[8];
    const float* thf = (const float*)d_in[9];
    const float* thi = (const float*)d_in[10];
    const float* thu = (const float*)d_in[11];
    const float* tho = (const float*)d_in[12];
    float* out = (float*)d_out;

    k1_gemm<<<128, 256>>>(X, Wf, bf, Wi, bi, Wu, bu, Wo, bo, thf, thi, thu, tho);
    k2_scan<<<32, 128>>>(Wf, Wi, Wu, Wo, out);
}

// round 17
// speedup vs baseline: 1.1968x; 1.1968x over previous
#include <cuda_runtime.h>

#define TT 64
#define BB 256
#define DD 512

// pre-activations, K2-block-contiguous layout:
// g_pre2[bblk(32)][t(64)][bloc(8)][gate(4)][q(6)]
__device__ __align__(16) float g_pre2[TT * BB * 24];

#define WGSTR 1544   // per-gate W section stride (floats); 1544*4B: 16B-aligned,
                     // and 1544 mod 32 = 8 -> gate sections offset 8 banks apart

// ---------------------------------------------------------------------------
// K1: pre[t,b,g,q] = inputs[t,b,:] @ Wg[:512,q] + bg[q] + theta_g[q]
// R14 kernel + gate-major W layout: Wph[g*WGSTR + dd*6 + q]. Per d the 6
// weights are contiguous; alignment parity is compile-time (24B*d), so the
// fetch is LDS.128+LDS.64 (2 LDS) instead of 3x LDS.64. Staging remains one
// unpredicated STS per element. Everything else identical to R14 (41.7 best).
// ---------------------------------------------------------------------------
__global__ void __launch_bounds__(256, 1) k1_gemm(
    const float* __restrict__ X,
    const float* __restrict__ Wf, const float* __restrict__ bf,
    const float* __restrict__ Wi, const float* __restrict__ bi,
    const float* __restrict__ Wu, const float* __restrict__ bu,
    const float* __restrict__ Wo, const float* __restrict__ bo,
    const float* __restrict__ thf, const float* __restrict__ thi,
    const float* __restrict__ thu, const float* __restrict__ tho)
{
    __shared__ __align__(16) float Wph[4 * WGSTR];  // gate-major K-half of W, 24.7KB
    __shared__ float Xsh[32 * 130];                 // x tile transposed [d][row]

    const int tid  = threadIdx.x;
    const int warp = tid >> 5;
    const int lane = tid & 31;
    const int gate = warp & 3;
    const int rloc = ((warp >> 2) << 6) + (lane << 1);   // block-local row (even)
    const int rowbase = blockIdx.x << 7;

    const float* bg = (gate == 0) ? bf  : (gate == 1) ? bi  : (gate == 2) ? bu  : bo;
    const float* tg = (gate == 0) ? thf : (gate == 1) ? thi : (gate == 2) ? thu : tho;

    unsigned long long a0[3], a1[3];
#pragma unroll
    for (int p = 0; p < 3; p++) {
        float blo = __ldg(bg + 2 * p + 0) + __ldg(tg + 2 * p + 0);
        float bhi = __ldg(bg + 2 * p + 1) + __ldg(tg + 2 * p + 1);
        unsigned long long bp;
        asm("mov.b64 %0, {%1, %2};" : "=l"(bp) : "f"(blo), "f"(bhi));
        a0[p] = bp;
        a1[p] = bp;
    }

    const int cc = tid & 7;   // d-group for staging
    const int rr = tid >> 3;  // row for staging

    // prologue: prefetch X tile 0 into registers
    float4 xr0, xr1, xr2, xr3;
    {
        const float4* xb = reinterpret_cast<const float4*>(X) + cc;
        xr0 = __ldg(xb + (size_t)(rowbase + rr +  0) * (DD / 4));
        xr1 = __ldg(xb + (size_t)(rowbase + rr + 32) * (DD / 4));
        xr2 = __ldg(xb + (size_t)(rowbase + rr + 64) * (DD / 4));
        xr3 = __ldg(xb + (size_t)(rowbase + rr + 96) * (DD / 4));
    }

    const float* wgbase = Wph + gate * WGSTR;

    for (int kh = 0; kh < 2; kh++) {
        __syncthreads();  // prior compute done before Wph overwrite
        // stage W half kh, gate-major: Wph[g2*WGSTR + dd*6 + q2]
#pragma unroll
        for (int k = 0; k < 24; k++) {
            int idx = tid + (k << 8);          // 0..6143 == dd*24 + col
            int dd  = idx / 24;
            int col = idx - dd * 24;
            int g2  = col / 6;
            int q2  = col - g2 * 6;
            const float* Ws = (g2 == 0) ? Wf : (g2 == 1) ? Wi : (g2 == 2) ? Wu : Wo;
            Wph[g2 * WGSTR + dd * 6 + q2] = Ws[((kh << 8) + dd) * 6 + q2];
        }
        for (int tile = 0; tile < 8; tile++) {
            __syncthreads();  // Wph ready (tile 0) / Xsh free (prior compute done)
            {
                const int c4 = cc << 2;
                Xsh[(c4 + 0) * 130 + rr +  0] = xr0.x;
                Xsh[(c4 + 1) * 130 + rr +  0] = xr0.y;
                Xsh[(c4 + 2) * 130 + rr +  0] = xr0.z;
                Xsh[(c4 + 3) * 130 + rr +  0] = xr0.w;
                Xsh[(c4 + 0) * 130 + rr + 32] = xr1.x;
                Xsh[(c4 + 1) * 130 + rr + 32] = xr1.y;
                Xsh[(c4 + 2) * 130 + rr + 32] = xr1.z;
                Xsh[(c4 + 3) * 130 + rr + 32] = xr1.w;
                Xsh[(c4 + 0) * 130 + rr + 64] = xr2.x;
                Xsh[(c4 + 1) * 130 + rr + 64] = xr2.y;
                Xsh[(c4 + 2) * 130 + rr + 64] = xr2.z;
                Xsh[(c4 + 3) * 130 + rr + 64] = xr2.w;
                Xsh[(c4 + 0) * 130 + rr + 96] = xr3.x;
                Xsh[(c4 + 1) * 130 + rr + 96] = xr3.y;
                Xsh[(c4 + 2) * 130 + rr + 96] = xr3.z;
                Xsh[(c4 + 3) * 130 + rr + 96] = xr3.w;
            }
            __syncthreads();  // Xsh ready

            const int gtn = (kh << 3) + tile + 1;
            if (gtn < 16) {
                const float4* xb = reinterpret_cast<const float4*>(X) + (gtn << 3) + cc;
                xr0 = __ldg(xb + (size_t)(rowbase + rr +  0) * (DD / 4));
                xr1 = __ldg(xb + (size_t)(rowbase + rr + 32) * (DD / 4));
                xr2 = __ldg(xb + (size_t)(rowbase + rr + 64) * (DD / 4));
                xr3 = __ldg(xb + (size_t)(rowbase + rr + 96) * (DD / 4));
            }

#pragma unroll
            for (int d = 0; d < 32; d++) {
                const float* wd = wgbase + (tile << 5) * 6 + d * 6;
                unsigned long long w01, w23, w45;
                if ((d & 1) == 0) {
                    // 24B*d with even d: 16B-aligned
                    const ulonglong2 v = *reinterpret_cast<const ulonglong2*>(wd);
                    w01 = v.x;
                    w23 = v.y;
                    w45 = *reinterpret_cast<const unsigned long long*>(wd + 4);
                } else {
                    // base ≡ 8 mod 16; wd+2 is 16B-aligned
                    w01 = *reinterpret_cast<const unsigned long long*>(wd);
                    const ulonglong2 v = *reinterpret_cast<const ulonglong2*>(wd + 2);
                    w23 = v.x;
                    w45 = v.y;
                }
                const float2 x2 = *reinterpret_cast<const float2*>(&Xsh[d * 130 + rloc]);
                unsigned long long xa, xb2;
                asm("mov.b64 %0, {%1, %1};" : "=l"(xa)  : "f"(x2.x));
                asm("mov.b64 %0, {%1, %1};" : "=l"(xb2) : "f"(x2.y));
                asm("fma.rn.f32x2 %0, %1, %2, %0;" : "+l"(a0[0]) : "l"(w01), "l"(xa));
                asm("fma.rn.f32x2 %0, %1, %2, %0;" : "+l"(a0[1]) : "l"(w23), "l"(xa));
                asm("fma.rn.f32x2 %0, %1, %2, %0;" : "+l"(a0[2]) : "l"(w45), "l"(xa));
                asm("fma.rn.f32x2 %0, %1, %2, %0;" : "+l"(a1[0]) : "l"(w01), "l"(xb2));
                asm("fma.rn.f32x2 %0, %1, %2, %0;" : "+l"(a1[1]) : "l"(w23), "l"(xb2));
                asm("fma.rn.f32x2 %0, %1, %2, %0;" : "+l"(a1[2]) : "l"(w45), "l"(xb2));
            }
        }
    }

    const int t = rowbase >> 8;
    const int b = (rowbase & 255) + rloc;       // even; b+1 shares b>>3
    float* dst = g_pre2 + ((size_t)((b >> 3) * 64 + t) * 192) + (b & 7) * 24 + gate * 6;
    unsigned long long* d64 = reinterpret_cast<unsigned long long*>(dst);
    d64[0] = a0[0]; d64[1] = a0[1]; d64[2] = a0[2];
    unsigned long long* e64 = reinterpret_cast<unsigned long long*>(dst + 24);
    e64[0] = a1[0]; e64[1] = a1[1]; e64[2] = a1[2];
}

// tanh via CF rational, one rcp; err <= ~2e-5 for |x| <= 2.2 (|c| <= 2.08).
__device__ __forceinline__ float tanh_rat(float x) {
    float s = x * x;
    float num = fmaf(s, fmaf(s, 21.0f, 1260.0f), 10395.0f);
    float den = fmaf(s, fmaf(s, s + 210.0f, 4725.0f), 10395.0f);
    float r;
    asm("rcp.approx.f32 %0, %1;" : "=f"(r) : "f"(den));
    return x * num * r;
}

// ---------------------------------------------------------------------------
// K2: EXACT R11 kernel (best measured: 17.2us).
// ---------------------------------------------------------------------------
__global__ void __launch_bounds__(128, 1) k2_scan(
    const float* __restrict__ Wf, const float* __restrict__ Wi,
    const float* __restrict__ Wu, const float* __restrict__ Wo,
    float* __restrict__ out)
{
    __shared__ float ps[TT * 192];    // 48KB : [t][bloc(8)][gate][q]

    const int tid = threadIdx.x;

    {
        const float4* src = reinterpret_cast<const float4*>(g_pre2 + (size_t)blockIdx.x * (TT * 192));
        float4* dst = reinterpret_cast<float4*>(ps);
#pragma unroll
        for (int i = 0; i < (TT * 192) / 4 / 128; i++)
            dst[tid + i * 128] = src[tid + i * 128];
    }
    __syncthreads();
    if (tid >= 64) return;

    const int lane = tid & 31;
    const int wrp  = tid >> 5;            // 0 or 1
    const int qh   = lane & 1;            // wire half
    const int g    = (lane >> 1) & 3;     // gate
    const int bl   = lane >> 3;           // batch within warp (0..3)
    const int bloc = (wrp << 2) + bl;     // batch within block (0..7)
    const int b    = (blockIdx.x << 3) + bloc;
    const int q0   = 3 * qh;
    const float* Wg = (g == 0) ? Wf : (g == 1) ? Wi : (g == 2) ? Wu : Wo;

    float Whk[6][3];
#pragma unroll
    for (int k = 0; k < 6; k++)
#pragma unroll
        for (int j = 0; j < 3; j++)
            Whk[k][j] = __ldg(Wg + (DD + k) * 6 + q0 + j);

    float h6[6];
#pragma unroll
    for (int k = 0; k < 6; k++) h6[k] = 0.0f;
    float c[3] = { 0.0f, 0.0f, 0.0f };

    const float* pb = ps + bloc * 24 + g * 6 + q0;
    const unsigned mask = 0xffffffffu;
    const int lb  = (lane & 24) | qh;     // gate-0 lane of this (batch, qh)
    const bool isU = (g == 2);
    const float cmul = isU ? -2.0f : -1.0f;
    const bool store = (g == 0);

#pragma unroll 2
    for (int t = 0; t < TT; t++) {
        const float p0 = pb[t * 192 + 0];
        const float p1 = pb[t * 192 + 1];
        const float p2 = pb[t * 192 + 2];

        float a[3];
        {
            float pj[3] = { p0, p1, p2 };
#pragma unroll
            for (int j = 0; j < 3; j++) {
                float u0 = fmaf(h6[0], Whk[0][j], fmaf(h6[1], Whk[1][j], fmaf(h6[2], Whk[2][j], pj[j])));
                float u1 = fmaf(h6[3], Whk[3][j], fmaf(h6[4], Whk[4][j], h6[5] * Whk[5][j]));
                a[j] = u0 + u1;
            }
        }

        float z0 = __cosf(a[0]);
        float z1 = __cosf(a[1]);
        float z2 = __cosf(a[2]);

        float zp0 = __shfl_xor_sync(mask, z0, 1);
        float zp1 = __shfl_xor_sync(mask, z1, 1);
        float zp2 = __shfl_xor_sync(mask, z2, 1);
        float zA0 = qh ? zp0 : z0;   // q0
        float zA1 = qh ? zp1 : z1;   // q1
        float zA2 = qh ? zp2 : z2;   // q2
        float zB0 = qh ? z0 : zp0;   // q3
        float zB1 = qh ? z1 : zp1;   // q4
        float zB2 = qh ? z2 : zp2;   // q5

        float z01 = zA0 * zA1;
        float z23 = zA2 * zB0;
        float z45 = zB1 * zB2;
        float w3  = z01 * z23;
        float wv0 = qh ? w3        : zA1 * (z23 * z45);   // w3 : w0
        float wv1 = qh ? w3 * zB1  : z01;                 // w4 : w1
        float wv2 = qh ? w3 * z45  : z01 * zA2;           // w5 : w2

        float v0, v1, v2;
        {
            float e0 = __expf(cmul * wv0);
            float e1 = __expf(cmul * wv1);
            float e2 = __expf(cmul * wv2);
            float s0 = __fdividef(1.0f, 1.0f + e0);
            float s1 = __fdividef(1.0f, 1.0f + e1);
            float s2 = __fdividef(1.0f, 1.0f + e2);
            v0 = isU ? fmaf(2.0f, s0, -1.0f) : s0;
            v1 = isU ? fmaf(2.0f, s1, -1.0f) : s1;
            v2 = isU ? fmaf(2.0f, s2, -1.0f) : s2;
        }

        float hq[3];
#pragma unroll
        for (int j = 0; j < 3; j++) {
            float vj = (j == 0) ? v0 : (j == 1) ? v1 : v2;
            float fq = __shfl_sync(mask, vj, lb + 0);
            float iq = __shfl_sync(mask, vj, lb + 2);
            float uq = __shfl_sync(mask, vj, lb + 4);
            float oq = __shfl_sync(mask, vj, lb + 6);
            float cn = fmaf(fq, c[j], iq * uq);
            c[j] = cn;
            hq[j] = oq * tanh_rat(cn);     // |cn| <= 2.08 guaranteed
        }

        if (store) {
            float* o0 = out + ((size_t)t * BB + b) * 6 + q0;
            o0[0] = hq[0]; o0[1] = hq[1]; o0[2] = hq[2];
        }

        float hp0 = __shfl_xor_sync(mask, hq[0], 1);
        float hp1 = __shfl_xor_sync(mask, hq[1], 1);
        float hp2 = __shfl_xor_sync(mask, hq[2], 1);
        h6[0] = qh ? hp0 : hq[0];
        h6[1] = qh ? hp1 : hq[1];
        h6[2] = qh ? hp2 : hq[2];
        h6[3] = qh ? hq[0] : hp0;
        h6[4] = qh ? hq[1] : hp1;
        h6[5] = qh ? hq[2] : hp2;
    }

    if (store) {
        float* hx = out + (size_t)TT * BB * 6 + (size_t)b * 6 + q0;
        float* cx = hx + BB * 6;
        hx[0] = qh ? h6[3] : h6[0];
        hx[1] = qh ? h6[4] : h6[1];
        hx[2] = qh ? h6[5] : h6[2];
        cx[0] = c[0]; cx[1] = c[1]; cx[2] = c[2];
    }
}

extern "C" void kernel_launch(void* const* d_in, const int* in_sizes, int n_in,
                              void* d_out, int out_size)
{
    const float* X   = (const float*)d_in[0];
    const float* Wf  = (const float*)d_in[1];
    const float* bf  = (const float*)d_in[2];
    const float* Wi  = (const float*)d_in[3];
    const float* bi  = (const float*)d_in[4];
    const float* Wu  = (const float*)d_in[5];
    const float* bu  = (const float*)d_in[6];
    const float* Wo  = (const float*)d_in[7];
    const float* bo  = (const float*)d_in[8];
    const float* thf = (const float*)d_in[9];
    const float* thi = (const float*)d_in[10];
    const float* thu = (const float*)d_in[11];
    const float* tho = (const float*)d_in[12];
    float* out = (float*)d_out;

    k1_gemm<<<128, 256>>>(X, Wf, bf, Wi, bi, Wu, bu, Wo, bo, thf, thi, thu, tho);
    k2_scan<<<32, 128>>>(Wf, Wi, Wu, Wo, out);
}